// round 1
// baseline (speedup 1.0000x reference)
#include <cuda_runtime.h>
#include <cstdint>

#define NN 100000
#define EE 1600000
#define HH 64
#define CC 10
#define GG 1000
#define BN_EPS 1e-5f

// ---------------- scratch (static device globals; no runtime allocation) ----
__device__ float g_agg[NN * HH];
__device__ float g_t[NN * HH];
__device__ float g_u[NN * HH];
__device__ float g_h1[NN * HH];
__device__ float g_h2[NN * HH];
__device__ float g_stat[4 * HH];           // [0:64) sum1, [64:128) sq1, [128:192) sum2, [192:256) sq2
__device__ float g_pooled[3 * GG * HH];    // per-layer global_add_pool outputs

// ---------------- index-width detection (int64 vs int32 payload) ------------
// If data is true int64, odd 32-bit words are high words == 0 (values < 2^31).
// If data is int32, those words are actual (random / nonzero) values.
__device__ __forceinline__ bool edge_is64(const void* p) {
    const int* q = (const int*)p;
    return (q[1] | q[3] | q[5] | q[7]) == 0;
}
__device__ __forceinline__ bool batch_is64(const void* p) {
    // batch is sorted starting at 0, so probe near the END (still within the
    // smaller int32 footprint of NN ints). Odd indices = int64 high words.
    const int* q = (const int*)p;
    return (q[NN - 1] | q[NN - 3] | q[NN - 5] | q[NN - 7]) == 0;
}

// ---------------- scatter-add: agg[dst] += h[src] over all edges ------------
__global__ void scatter_kernel(const float* __restrict__ h,
                               const void* __restrict__ eidx,
                               float* __restrict__ agg) {
    long e = (long)blockIdx.x * blockDim.x + threadIdx.x;
    if (e >= EE) return;
    const bool is64 = edge_is64(eidx);
    int s, d;
    if (is64) {
        const long long* q = (const long long*)eidx;
        s = (int)q[e];
        d = (int)q[EE + e];
    } else {
        const int* q = (const int*)eidx;
        s = q[e];
        d = q[EE + e];
    }
    const float4* hv = (const float4*)(h + (size_t)s * HH);
    float* base = agg + (size_t)d * HH;
#pragma unroll
    for (int q4 = 0; q4 < 16; q4++) {
        float4 v = hv[q4];
        asm volatile("red.global.add.v4.f32 [%0], {%1,%2,%3,%4};"
                     :: "l"(base + q4 * 4), "f"(v.x), "f"(v.y), "f"(v.z), "f"(v.w)
                     : "memory");
    }
}

// ---------------- fused 64x64 GEMM ------------------------------------------
// out[r,:] = f(A[r,:] (+ A2[r,:]))  @ W + bias
//   ADD2:  input = A + A2               (GIN: h + agg)
//   BNIN:  input = relu(bn(A)) using column stats (sum, sumsq) + gamma/beta
// 4 threads per row, 16 outputs per thread; W cached in smem.
template <bool ADD2, bool BNIN>
__global__ void __launch_bounds__(256) gemm_kernel(
    const float* __restrict__ A, const float* __restrict__ A2,
    const float* __restrict__ ssum, const float* __restrict__ ssq,
    const float* __restrict__ gam, const float* __restrict__ bet,
    const float* __restrict__ W, const float* __restrict__ bias,
    float* __restrict__ out) {
    __shared__ float sW[HH * HH];
    __shared__ float sB[HH];
    __shared__ float sS[HH];
    __shared__ float sO[HH];
    const int tid = threadIdx.x;

    float4* sW4 = (float4*)sW;
    const float4* W4 = (const float4*)W;
#pragma unroll
    for (int i = 0; i < 4; i++) sW4[tid + i * 256] = W4[tid + i * 256];
    if (tid < HH) {
        sB[tid] = bias[tid];
        if (BNIN) {
            float m = ssum[tid] * (1.0f / NN);
            float v = ssq[tid] * (1.0f / NN) - m * m;
            float inv = rsqrtf(v + BN_EPS);
            float s = gam[tid] * inv;
            sS[tid] = s;
            sO[tid] = bet[tid] - m * s;
        }
    }
    __syncthreads();

    const int r = blockIdx.x * 64 + (tid >> 2);
    if (r >= NN) return;
    const int j0 = (tid & 3) * 16;

    const float4* a4 = (const float4*)(A + (size_t)r * HH);
    float4 z[16];
#pragma unroll
    for (int c = 0; c < 16; c++) {
        float4 v = a4[c];
        if (ADD2) {
            float4 w = ((const float4*)(A2 + (size_t)r * HH))[c];
            v.x += w.x; v.y += w.y; v.z += w.z; v.w += w.w;
        }
        if (BNIN) {
            int k = c * 4;
            v.x = fmaxf(fmaf(v.x, sS[k + 0], sO[k + 0]), 0.f);
            v.y = fmaxf(fmaf(v.y, sS[k + 1], sO[k + 1]), 0.f);
            v.z = fmaxf(fmaf(v.z, sS[k + 2], sO[k + 2]), 0.f);
            v.w = fmaxf(fmaf(v.w, sS[k + 3], sO[k + 3]), 0.f);
        }
        z[c] = v;
    }

    float acc[16];
#pragma unroll
    for (int i = 0; i < 16; i++) acc[i] = sB[j0 + i];

#pragma unroll
    for (int c = 0; c < 16; c++) {
        float zs[4] = {z[c].x, z[c].y, z[c].z, z[c].w};
#pragma unroll
        for (int kk = 0; kk < 4; kk++) {
            const float zk = zs[kk];
            const float4* wr4 = (const float4*)(sW + (c * 4 + kk) * HH + j0);
#pragma unroll
            for (int i = 0; i < 4; i++) {
                float4 w = wr4[i];
                acc[i * 4 + 0] = fmaf(zk, w.x, acc[i * 4 + 0]);
                acc[i * 4 + 1] = fmaf(zk, w.y, acc[i * 4 + 1]);
                acc[i * 4 + 2] = fmaf(zk, w.z, acc[i * 4 + 2]);
                acc[i * 4 + 3] = fmaf(zk, w.w, acc[i * 4 + 3]);
            }
        }
    }

    float4* o4 = (float4*)(out + (size_t)r * HH + j0);
    o4[0] = make_float4(acc[0], acc[1], acc[2], acc[3]);
    o4[1] = make_float4(acc[4], acc[5], acc[6], acc[7]);
    o4[2] = make_float4(acc[8], acc[9], acc[10], acc[11]);
    o4[3] = make_float4(acc[12], acc[13], acc[14], acc[15]);
}

// ---------------- per-column sum & sum of squares ---------------------------
__global__ void colstats_kernel(const float* __restrict__ X,
                                float* __restrict__ osum,
                                float* __restrict__ osq) {
    __shared__ float ssum[256], ssq[256];
    const int tid = threadIdx.x;
    const int c = tid & 63;
    int r = blockIdx.x * 4 + (tid >> 6);
    const int stride = gridDim.x * 4;
    float s = 0.f, q = 0.f;
    for (; r < NN; r += stride) {
        float v = X[(size_t)r * 64 + c];
        s += v;
        q += v * v;
    }
    ssum[tid] = s;
    ssq[tid] = q;
    __syncthreads();
    if (tid < 64) {
        s = ssum[tid] + ssum[tid + 64] + ssum[tid + 128] + ssum[tid + 192];
        q = ssq[tid] + ssq[tid + 64] + ssq[tid + 128] + ssq[tid + 192];
        atomicAdd(&osum[tid], s);
        atomicAdd(&osq[tid], q);
    }
}

// ---------------- elementwise bn + relu -------------------------------------
__global__ void bnrelu_kernel(const float* __restrict__ X,
                              const float* __restrict__ ssum,
                              const float* __restrict__ ssq,
                              const float* __restrict__ gam,
                              const float* __restrict__ bet,
                              float* __restrict__ out) {
    __shared__ float sS[64], sO[64];
    const int tid = threadIdx.x;
    if (tid < 64) {
        float m = ssum[tid] * (1.0f / NN);
        float v = ssq[tid] * (1.0f / NN) - m * m;
        float inv = rsqrtf(v + BN_EPS);
        float s = gam[tid] * inv;
        sS[tid] = s;
        sO[tid] = bet[tid] - m * s;
    }
    __syncthreads();
    long i = (long)blockIdx.x * 256 + tid;
    if (i >= (long)NN * 16) return;
    const int k = (int)(i & 15) * 4;
    float4 v = ((const float4*)X)[i];
    v.x = fmaxf(fmaf(v.x, sS[k + 0], sO[k + 0]), 0.f);
    v.y = fmaxf(fmaf(v.y, sS[k + 1], sO[k + 1]), 0.f);
    v.z = fmaxf(fmaf(v.z, sS[k + 2], sO[k + 2]), 0.f);
    v.w = fmaxf(fmaf(v.w, sS[k + 3], sO[k + 3]), 0.f);
    ((float4*)out)[i] = v;
}

// ---------------- pooled[batch[r]] += h[r]  (batch is sorted) ---------------
__global__ void pool_kernel(const float* __restrict__ h,
                            const void* __restrict__ batch,
                            float* __restrict__ pooled) {
    const int f = threadIdx.x;  // 64 threads, one per feature
    const int r0 = blockIdx.x * 512;
    const int r1 = min(r0 + 512, NN);
    const bool is64 = batch_is64(batch);
    float acc = 0.f;
    int cur = -1;
    for (int r = r0; r < r1; ++r) {
        int g = is64 ? (int)((const long long*)batch)[r]
                     : ((const int*)batch)[r];
        if (g != cur) {
            if (cur >= 0) atomicAdd(&pooled[(size_t)cur * 64 + f], acc);
            acc = 0.f;
            cur = g;
        }
        acc += h[(size_t)r * 64 + f];
    }
    if (cur >= 0) atomicAdd(&pooled[(size_t)cur * 64 + f], acc);
}

// ---------------- final jumping-knowledge readout ----------------------------
__global__ void readout_kernel(const float* __restrict__ w0, const float* __restrict__ b0,
                               const float* __restrict__ w1, const float* __restrict__ b1,
                               const float* __restrict__ w2, const float* __restrict__ b2,
                               float* __restrict__ out) {
    int t = blockIdx.x * blockDim.x + threadIdx.x;
    if (t >= GG * CC) return;
    int g = t / CC, c = t % CC;
    float acc = b0[c] + b1[c] + b2[c];
    const float* p0 = g_pooled + (size_t)g * 64;
    const float* p1 = g_pooled + (size_t)GG * 64 + (size_t)g * 64;
    const float* p2 = g_pooled + (size_t)2 * GG * 64 + (size_t)g * 64;
#pragma unroll
    for (int f = 0; f < 64; f++) {
        acc = fmaf(p0[f], w0[f * CC + c], acc);
        acc = fmaf(p1[f], w1[f * CC + c], acc);
        acc = fmaf(p2[f], w2[f * CC + c], acc);
    }
    out[t] = acc;
}

// ---------------- launch -----------------------------------------------------
extern "C" void kernel_launch(void* const* d_in, const int* in_sizes, int n_in,
                              void* d_out, int out_size) {
    const float* x = (const float*)d_in[0];
    const void* eidx = d_in[1];
    const void* batch = d_in[2];

    void *aggp, *tp, *up, *h1p, *h2p, *statp, *pooledp;
    cudaGetSymbolAddress(&aggp, g_agg);
    cudaGetSymbolAddress(&tp, g_t);
    cudaGetSymbolAddress(&up, g_u);
    cudaGetSymbolAddress(&h1p, g_h1);
    cudaGetSymbolAddress(&h2p, g_h2);
    cudaGetSymbolAddress(&statp, g_stat);
    cudaGetSymbolAddress(&pooledp, g_pooled);

    float* agg = (float*)aggp;
    float* t = (float*)tp;
    float* u = (float*)up;
    float* stat = (float*)statp;
    float* pooled = (float*)pooledp;
    float* houts[2] = {(float*)h1p, (float*)h2p};

    const int GEMM_BLOCKS = (NN + 63) / 64;       // 1563
    const int SCAT_BLOCKS = (EE + 255) / 256;     // 6250
    const int ELEM_BLOCKS = (NN * 16 + 255) / 256;// 6250
    const int POOL_BLOCKS = (NN + 511) / 512;     // 196

    // pooled = 0; pool layer-0 features (x)
    cudaMemsetAsync(pooled, 0, (size_t)3 * GG * HH * sizeof(float), 0);
    pool_kernel<<<POOL_BLOCKS, 64>>>(x, batch, pooled);

    const float* hin = x;
    for (int l = 0; l < 2; l++) {
        const int b = 3 + l * 8;
        const float* w1  = (const float*)d_in[b + 0];
        const float* b1  = (const float*)d_in[b + 1];
        const float* g1  = (const float*)d_in[b + 2];
        const float* be1 = (const float*)d_in[b + 3];
        const float* w2  = (const float*)d_in[b + 4];
        const float* b2  = (const float*)d_in[b + 5];
        const float* bng = (const float*)d_in[b + 6];
        const float* bnb = (const float*)d_in[b + 7];
        float* hout = houts[l];

        cudaMemsetAsync(agg, 0, (size_t)NN * HH * sizeof(float), 0);
        cudaMemsetAsync(stat, 0, 4 * HH * sizeof(float), 0);

        scatter_kernel<<<SCAT_BLOCKS, 256>>>(hin, eidx, agg);

        // t = (h + agg) @ w1 + b1
        gemm_kernel<true, false><<<GEMM_BLOCKS, 256>>>(
            hin, agg, nullptr, nullptr, nullptr, nullptr, w1, b1, t);

        colstats_kernel<<<512, 256>>>(t, stat, stat + 64);

        // u = relu(bn(t; g1, be1)) @ w2 + b2
        gemm_kernel<false, true><<<GEMM_BLOCKS, 256>>>(
            t, nullptr, stat, stat + 64, g1, be1, w2, b2, u);

        colstats_kernel<<<512, 256>>>(u, stat + 128, stat + 192);

        // h_next = relu(bn(u; bng, bnb))
        bnrelu_kernel<<<ELEM_BLOCKS, 256>>>(u, stat + 128, stat + 192, bng, bnb, hout);

        pool_kernel<<<POOL_BLOCKS, 64>>>(hout, batch, pooled + (size_t)(l + 1) * GG * HH);

        hin = hout;
    }

    readout_kernel<<<(GG * CC + 255) / 256, 256>>>(
        (const float*)d_in[19], (const float*)d_in[20],
        (const float*)d_in[21], (const float*)d_in[22],
        (const float*)d_in[23], (const float*)d_in[24],
        (float*)d_out);
}

// round 2
// speedup vs baseline: 1.7217x; 1.7217x over previous
#include <cuda_runtime.h>
#include <cstdint>

#define NN 100000
#define EE 1600000
#define HH 64
#define CC 10
#define GG 1000
#define BN_EPS 1e-5f

// ---------------- scratch (static device globals) ---------------------------
__device__ float g_z[NN * HH];          // z (agg+self) for gemm1; reused as u (gemm2 out)
__device__ float g_t[NN * HH];          // gemm1 output
__device__ float g_h1[NN * HH];
__device__ float g_h2[NN * HH];
__device__ float g_stat[8 * 64];        // per layer: t sum/sq, u sum/sq
__device__ float g_pooled[3 * GG * HH];
__device__ int   g_cnt[NN];
__device__ int   g_indptr[NN + 1];
__device__ int   g_cursor[NN];
__device__ int   g_srcs[EE];
__device__ int   g_bsum[512];

#define SCAN_BLOCKS 391   // ceil(100000/256)

// ---------------- index-width detection (int64 vs int32 payload) ------------
__device__ __forceinline__ bool edge_is64(const void* p) {
    const int* q = (const int*)p;
    return (q[1] | q[3] | q[5] | q[7]) == 0;
}
__device__ __forceinline__ bool batch_is64(const void* p) {
    const int* q = (const int*)p;
    return (q[NN - 1] | q[NN - 3] | q[NN - 5] | q[NN - 7]) == 0;
}

// ---------------- CSR build --------------------------------------------------
__global__ void count_kernel(const void* __restrict__ eidx, int* __restrict__ cnt) {
    int e = blockIdx.x * 256 + threadIdx.x;       // grid exact: EE/256
    int d = edge_is64(eidx) ? (int)((const long long*)eidx)[EE + e]
                            : ((const int*)eidx)[EE + e];
    atomicAdd(&cnt[d], 1);
}

__global__ void scanA_kernel(const int* __restrict__ cnt, int* __restrict__ bsum) {
    __shared__ int sd[256];
    int i = blockIdx.x * 256 + threadIdx.x;
    sd[threadIdx.x] = (i < NN) ? cnt[i] : 0;
    __syncthreads();
    for (int off = 128; off > 0; off >>= 1) {
        if (threadIdx.x < off) sd[threadIdx.x] += sd[threadIdx.x + off];
        __syncthreads();
    }
    if (threadIdx.x == 0) bsum[blockIdx.x] = sd[0];
}

__global__ void scanB_kernel(int* __restrict__ bsum, int* __restrict__ indptr) {
    if (threadIdx.x == 0) {
        int acc = 0;
        for (int i = 0; i < SCAN_BLOCKS; i++) { int v = bsum[i]; bsum[i] = acc; acc += v; }
        indptr[NN] = EE;
    }
}

__global__ void scanC_kernel(const int* __restrict__ cnt, const int* __restrict__ bsum,
                             int* __restrict__ indptr, int* __restrict__ cursor) {
    __shared__ int sd[256];
    int i = blockIdx.x * 256 + threadIdx.x;
    int c = (i < NN) ? cnt[i] : 0;
    sd[threadIdx.x] = c;
    __syncthreads();
    for (int off = 1; off < 256; off <<= 1) {
        int v = (threadIdx.x >= off) ? sd[threadIdx.x - off] : 0;
        __syncthreads();
        sd[threadIdx.x] += v;
        __syncthreads();
    }
    int excl = bsum[blockIdx.x] + sd[threadIdx.x] - c;
    if (i < NN) { indptr[i] = excl; cursor[i] = excl; }
}

__global__ void fill_kernel(const void* __restrict__ eidx, int* __restrict__ cursor,
                            int* __restrict__ srcs) {
    int e = blockIdx.x * 256 + threadIdx.x;
    int s, d;
    if (edge_is64(eidx)) {
        const long long* q = (const long long*)eidx;
        s = (int)q[e];
        d = (int)q[EE + e];
    } else {
        const int* q = (const int*)eidx;
        s = q[e];
        d = q[EE + e];
    }
    int pos = atomicAdd(&cursor[d], 1);
    srcs[pos] = s;
}

// ---------------- gather aggregation: z[n] = h[n] + sum_{e in CSR(n)} h[src] -
__global__ void __launch_bounds__(256) aggregate_kernel(
    const float* __restrict__ h, const int* __restrict__ indptr,
    const int* __restrict__ srcs, float* __restrict__ z) {
    int t = blockIdx.x * 256 + threadIdx.x;   // grid exact: NN*8/256
    int n = t >> 3, oct = t & 7;
    const float4* self = (const float4*)(h + (size_t)n * 64 + oct * 8);
    float4 a0 = self[0], a1 = self[1];
    int e = indptr[n];
    const int end = indptr[n + 1];
    for (; e + 2 <= end; e += 2) {
        int s0 = srcs[e], s1 = srcs[e + 1];
        const float4* p0 = (const float4*)(h + (size_t)s0 * 64 + oct * 8);
        const float4* p1 = (const float4*)(h + (size_t)s1 * 64 + oct * 8);
        float4 b0 = p0[0], b1 = p0[1], c0 = p1[0], c1 = p1[1];
        a0.x += b0.x + c0.x; a0.y += b0.y + c0.y; a0.z += b0.z + c0.z; a0.w += b0.w + c0.w;
        a1.x += b1.x + c1.x; a1.y += b1.y + c1.y; a1.z += b1.z + c1.z; a1.w += b1.w + c1.w;
    }
    if (e < end) {
        int s0 = srcs[e];
        const float4* p0 = (const float4*)(h + (size_t)s0 * 64 + oct * 8);
        float4 b0 = p0[0], b1 = p0[1];
        a0.x += b0.x; a0.y += b0.y; a0.z += b0.z; a0.w += b0.w;
        a1.x += b1.x; a1.y += b1.y; a1.z += b1.z; a1.w += b1.w;
    }
    float4* o = (float4*)(z + (size_t)n * 64 + oct * 8);
    o[0] = a0; o[1] = a1;
}

// ---------------- fused 64x64 GEMM with column-stats epilogue ----------------
// out = f(A) @ W + bias;  BNIN: f = relu(bn(.)) using (ssum_in, ssq_in, gam, bet)
// epilogue: atomically accumulate column sums & sumsq of out into (osum, osq)
template <bool BNIN>
__global__ void __launch_bounds__(256) gemm_kernel(
    const float* __restrict__ A,
    const float* __restrict__ ssum_in, const float* __restrict__ ssq_in,
    const float* __restrict__ gam, const float* __restrict__ bet,
    const float* __restrict__ W, const float* __restrict__ bias,
    float* __restrict__ out,
    float* __restrict__ osum, float* __restrict__ osq) {
    __shared__ float sW[HH * HH];
    __shared__ float sB[HH];
    __shared__ float sS[HH];
    __shared__ float sO[HH];
    __shared__ float sSum[HH];
    __shared__ float sSq[HH];
    const int tid = threadIdx.x;

    float4* sW4 = (float4*)sW;
    const float4* W4 = (const float4*)W;
#pragma unroll
    for (int i = 0; i < 4; i++) sW4[tid + i * 256] = W4[tid + i * 256];
    if (tid < HH) {
        sB[tid] = bias[tid];
        sSum[tid] = 0.f;
        sSq[tid] = 0.f;
        if (BNIN) {
            float m = ssum_in[tid] * (1.0f / NN);
            float v = ssq_in[tid] * (1.0f / NN) - m * m;
            float inv = rsqrtf(v + BN_EPS);
            float s = gam[tid] * inv;
            sS[tid] = s;
            sO[tid] = bet[tid] - m * s;
        }
    }
    __syncthreads();

    const int r = blockIdx.x * 64 + (tid >> 2);
    const bool valid = (r < NN);
    const int rl = valid ? r : (NN - 1);
    const int j0 = (tid & 3) * 16;

    const float4* a4 = (const float4*)(A + (size_t)rl * HH);
    float4 z[16];
#pragma unroll
    for (int c = 0; c < 16; c++) {
        float4 v = a4[c];
        if (BNIN) {
            int k = c * 4;
            v.x = fmaxf(fmaf(v.x, sS[k + 0], sO[k + 0]), 0.f);
            v.y = fmaxf(fmaf(v.y, sS[k + 1], sO[k + 1]), 0.f);
            v.z = fmaxf(fmaf(v.z, sS[k + 2], sO[k + 2]), 0.f);
            v.w = fmaxf(fmaf(v.w, sS[k + 3], sO[k + 3]), 0.f);
        }
        z[c] = v;
    }

    float acc[16];
#pragma unroll
    for (int i = 0; i < 16; i++) acc[i] = sB[j0 + i];

#pragma unroll
    for (int c = 0; c < 16; c++) {
        float zs[4] = {z[c].x, z[c].y, z[c].z, z[c].w};
#pragma unroll
        for (int kk = 0; kk < 4; kk++) {
            const float zk = zs[kk];
            const float4* wr4 = (const float4*)(sW + (c * 4 + kk) * HH + j0);
#pragma unroll
            for (int i = 0; i < 4; i++) {
                float4 w = wr4[i];
                acc[i * 4 + 0] = fmaf(zk, w.x, acc[i * 4 + 0]);
                acc[i * 4 + 1] = fmaf(zk, w.y, acc[i * 4 + 1]);
                acc[i * 4 + 2] = fmaf(zk, w.z, acc[i * 4 + 2]);
                acc[i * 4 + 3] = fmaf(zk, w.w, acc[i * 4 + 3]);
            }
        }
    }

    if (valid) {
        float4* o4 = (float4*)(out + (size_t)r * HH + j0);
        o4[0] = make_float4(acc[0], acc[1], acc[2], acc[3]);
        o4[1] = make_float4(acc[4], acc[5], acc[6], acc[7]);
        o4[2] = make_float4(acc[8], acc[9], acc[10], acc[11]);
        o4[3] = make_float4(acc[12], acc[13], acc[14], acc[15]);
    }

    // ---- stats epilogue: reduce acc over the warp's 8 rows, then smem, then global
    const int lane = tid & 31;
#pragma unroll
    for (int i = 0; i < 16; i++) {
        float s = valid ? acc[i] : 0.f;
        float q = s * s;
        s += __shfl_down_sync(0xffffffffu, s, 4);
        q += __shfl_down_sync(0xffffffffu, q, 4);
        s += __shfl_down_sync(0xffffffffu, s, 8);
        q += __shfl_down_sync(0xffffffffu, q, 8);
        s += __shfl_down_sync(0xffffffffu, s, 16);
        q += __shfl_down_sync(0xffffffffu, q, 16);
        if (lane < 4) {
            atomicAdd(&sSum[j0 + i], s);
            atomicAdd(&sSq[j0 + i], q);
        }
    }
    __syncthreads();
    if (tid < 64) {
        atomicAdd(&osum[tid], sSum[tid]);
        atomicAdd(&osq[tid], sSq[tid]);
    }
}

// ---------------- fused (bn+relu) + parallel pooling -------------------------
// BN=true : hout = relu(bn(X)); pooled[batch[row]] += hout
// BN=false: pooled[batch[row]] += X   (hout unused)
template <bool BN>
__global__ void bnpool_kernel(const float* __restrict__ X,
                              const float* __restrict__ ssum,
                              const float* __restrict__ ssq,
                              const float* __restrict__ gam,
                              const float* __restrict__ bet,
                              const void* __restrict__ batch,
                              float* __restrict__ hout,
                              float* __restrict__ pooled) {
    __shared__ float sS[64], sO[64];
    const int tid = threadIdx.x;
    if (BN) {
        if (tid < 64) {
            float m = ssum[tid] * (1.0f / NN);
            float v = ssq[tid] * (1.0f / NN) - m * m;
            float inv = rsqrtf(v + BN_EPS);
            float s = gam[tid] * inv;
            sS[tid] = s;
            sO[tid] = bet[tid] - m * s;
        }
        __syncthreads();
    }
    long i = (long)blockIdx.x * 256 + tid;   // grid exact: NN*16/256
    const int row = (int)(i >> 4);
    const int k = (int)(i & 15) * 4;
    float4 v = ((const float4*)X)[i];
    if (BN) {
        v.x = fmaxf(fmaf(v.x, sS[k + 0], sO[k + 0]), 0.f);
        v.y = fmaxf(fmaf(v.y, sS[k + 1], sO[k + 1]), 0.f);
        v.z = fmaxf(fmaf(v.z, sS[k + 2], sO[k + 2]), 0.f);
        v.w = fmaxf(fmaf(v.w, sS[k + 3], sO[k + 3]), 0.f);
        ((float4*)hout)[i] = v;
    }
    int g = batch_is64(batch) ? (int)((const long long*)batch)[row]
                              : ((const int*)batch)[row];
    float* base = pooled + (size_t)g * 64 + k;
    asm volatile("red.global.add.v4.f32 [%0], {%1,%2,%3,%4};"
                 :: "l"(base), "f"(v.x), "f"(v.y), "f"(v.z), "f"(v.w)
                 : "memory");
}

// ---------------- final jumping-knowledge readout ----------------------------
__global__ void readout_kernel(const float* __restrict__ w0, const float* __restrict__ b0,
                               const float* __restrict__ w1, const float* __restrict__ b1,
                               const float* __restrict__ w2, const float* __restrict__ b2,
                               float* __restrict__ out) {
    int t = blockIdx.x * blockDim.x + threadIdx.x;
    if (t >= GG * CC) return;
    int g = t / CC, c = t % CC;
    float acc = b0[c] + b1[c] + b2[c];
    const float* p0 = g_pooled + (size_t)g * 64;
    const float* p1 = g_pooled + (size_t)GG * 64 + (size_t)g * 64;
    const float* p2 = g_pooled + (size_t)2 * GG * 64 + (size_t)g * 64;
#pragma unroll
    for (int f = 0; f < 64; f++) {
        acc = fmaf(p0[f], w0[f * CC + c], acc);
        acc = fmaf(p1[f], w1[f * CC + c], acc);
        acc = fmaf(p2[f], w2[f * CC + c], acc);
    }
    out[t] = acc;
}

// ---------------- launch -----------------------------------------------------
extern "C" void kernel_launch(void* const* d_in, const int* in_sizes, int n_in,
                              void* d_out, int out_size) {
    const float* x = (const float*)d_in[0];
    const void* eidx = d_in[1];
    const void* batch = d_in[2];

    void *zp, *tp, *h1p, *h2p, *statp, *pooledp;
    void *cntp, *indp, *curp, *srcp, *bsump;
    cudaGetSymbolAddress(&zp, g_z);
    cudaGetSymbolAddress(&tp, g_t);
    cudaGetSymbolAddress(&h1p, g_h1);
    cudaGetSymbolAddress(&h2p, g_h2);
    cudaGetSymbolAddress(&statp, g_stat);
    cudaGetSymbolAddress(&pooledp, g_pooled);
    cudaGetSymbolAddress(&cntp, g_cnt);
    cudaGetSymbolAddress(&indp, g_indptr);
    cudaGetSymbolAddress(&curp, g_cursor);
    cudaGetSymbolAddress(&srcp, g_srcs);
    cudaGetSymbolAddress(&bsump, g_bsum);

    float* z = (float*)zp;
    float* t = (float*)tp;
    float* stat = (float*)statp;
    float* pooled = (float*)pooledp;
    float* houts[2] = {(float*)h1p, (float*)h2p};
    int* cnt = (int*)cntp;
    int* indptr = (int*)indp;
    int* cursor = (int*)curp;
    int* srcs = (int*)srcp;
    int* bsum = (int*)bsump;

    const int EDGE_BLOCKS = EE / 256;           // 6250
    const int GEMM_BLOCKS = (NN + 63) / 64;     // 1563
    const int AGG_BLOCKS = NN * 8 / 256;        // 3125
    const int ELEM_BLOCKS = NN * 16 / 256;      // 6250

    cudaMemsetAsync((void*)cnt, 0, NN * sizeof(int), 0);
    cudaMemsetAsync((void*)stat, 0, 8 * 64 * sizeof(float), 0);
    cudaMemsetAsync((void*)pooled, 0, (size_t)3 * GG * HH * sizeof(float), 0);

    // ---- CSR build (kernels 1-5)
    count_kernel<<<EDGE_BLOCKS, 256>>>(eidx, cnt);
    scanA_kernel<<<SCAN_BLOCKS, 256>>>(cnt, bsum);
    scanB_kernel<<<1, 32>>>(bsum, indptr);
    scanC_kernel<<<SCAN_BLOCKS, 256>>>(cnt, bsum, indptr, cursor);
    fill_kernel<<<EDGE_BLOCKS, 256>>>(eidx, cursor, srcs);

    const float* hin = x;
    for (int l = 0; l < 2; l++) {
        const int b = 3 + l * 8;
        const float* w1  = (const float*)d_in[b + 0];
        const float* b1  = (const float*)d_in[b + 1];
        const float* g1  = (const float*)d_in[b + 2];
        const float* be1 = (const float*)d_in[b + 3];
        const float* w2  = (const float*)d_in[b + 4];
        const float* b2  = (const float*)d_in[b + 5];
        const float* bng = (const float*)d_in[b + 6];
        const float* bnb = (const float*)d_in[b + 7];
        float* hout = houts[l];
        float* st = stat + l * 256;   // [0:64) t-sum [64:128) t-sq [128:192) u-sum [192:256) u-sq

        // kernel 6 (layer 0) = aggregate -> profiled by ncu -s 5 -c 1
        aggregate_kernel<<<AGG_BLOCKS, 256>>>(hin, indptr, srcs, z);

        // t = z @ w1 + b1 ; accumulate col stats of t
        gemm_kernel<false><<<GEMM_BLOCKS, 256>>>(
            z, nullptr, nullptr, nullptr, nullptr, w1, b1, t, st, st + 64);

        // u = relu(bn(t)) @ w2 + b2 ; accumulate col stats of u  (u stored in z buffer)
        gemm_kernel<true><<<GEMM_BLOCKS, 256>>>(
            t, st, st + 64, g1, be1, w2, b2, z, st + 128, st + 192);

        // h_next = relu(bn(u)); pooled[l+1] += h_next rows
        bnpool_kernel<true><<<ELEM_BLOCKS, 256>>>(
            z, st + 128, st + 192, bng, bnb, batch, hout,
            pooled + (size_t)(l + 1) * GG * HH);

        hin = hout;
    }

    // layer-0 pooling of raw x
    bnpool_kernel<false><<<ELEM_BLOCKS, 256>>>(
        x, nullptr, nullptr, nullptr, nullptr, batch, nullptr, pooled);

    readout_kernel<<<(GG * CC + 255) / 256, 256>>>(
        (const float*)d_in[19], (const float*)d_in[20],
        (const float*)d_in[21], (const float*)d_in[22],
        (const float*)d_in[23], (const float*)d_in[24],
        (float*)d_out);
}

// round 3
// speedup vs baseline: 3.0874x; 1.7932x over previous
#include <cuda_runtime.h>
#include <cstdint>

#define NN 100000
#define EE 1600000
#define HH 64
#define CC 10
#define GG 1000
#define BN_EPS 1e-5f
#define MTILE 256
#define ZSTR 65   // smem z row stride (conflict-free scalar reads)

// ---------------- scratch (static device globals) ---------------------------
__device__ float g_t[NN * HH];
__device__ float g_u[NN * HH];
__device__ float g_h1[NN * HH];
__device__ float g_h2[NN * HH];
__device__ float g_stat[8 * 64];
__device__ float g_pooled[3 * GG * HH];
__device__ int   g_cnt[NN];
__device__ int   g_indptr[NN + 1];
__device__ int   g_cursor[NN];
__device__ int   g_srcs[EE];
__device__ int   g_bsum[512];

#define SCAN_BLOCKS 391   // ceil(100000/256)

// ---------------- index-width detection --------------------------------------
__device__ __forceinline__ bool edge_is64(const void* p) {
    const int* q = (const int*)p;
    return (q[1] | q[3] | q[5] | q[7]) == 0;
}
__device__ __forceinline__ bool batch_is64(const void* p) {
    const int* q = (const int*)p;
    return (q[NN - 1] | q[NN - 3] | q[NN - 5] | q[NN - 7]) == 0;
}

__device__ __forceinline__ void add4(float4& a, const float4 b) {
    a.x += b.x; a.y += b.y; a.z += b.z; a.w += b.w;
}

// ---------------- init: zero cnt / stat / pooled ------------------------------
__global__ void init_kernel(int* __restrict__ cnt, float* __restrict__ stat,
                            float* __restrict__ pooled) {
    int i = blockIdx.x * 256 + threadIdx.x;
    if (i < NN) cnt[i] = 0;
    if (i < 8 * 64) stat[i] = 0.f;
    if (i < 3 * GG * HH) pooled[i] = 0.f;
}

// ---------------- CSR build ----------------------------------------------------
__global__ void count_kernel(const void* __restrict__ eidx, int* __restrict__ cnt) {
    int e = blockIdx.x * 256 + threadIdx.x;
    int d = edge_is64(eidx) ? (int)((const long long*)eidx)[EE + e]
                            : ((const int*)eidx)[EE + e];
    atomicAdd(&cnt[d], 1);
}

__global__ void scanA_kernel(const int* __restrict__ cnt, int* __restrict__ bsum) {
    __shared__ int sd[256];
    int i = blockIdx.x * 256 + threadIdx.x;
    sd[threadIdx.x] = (i < NN) ? cnt[i] : 0;
    __syncthreads();
    for (int off = 128; off > 0; off >>= 1) {
        if (threadIdx.x < off) sd[threadIdx.x] += sd[threadIdx.x + off];
        __syncthreads();
    }
    if (threadIdx.x == 0) bsum[blockIdx.x] = sd[0];
}

__global__ void scanB_kernel(int* __restrict__ bsum, int* __restrict__ indptr) {
    if (threadIdx.x == 0) {
        int acc = 0;
        for (int i = 0; i < SCAN_BLOCKS; i++) { int v = bsum[i]; bsum[i] = acc; acc += v; }
        indptr[NN] = EE;
    }
}

__global__ void scanC_kernel(const int* __restrict__ cnt, const int* __restrict__ bsum,
                             int* __restrict__ indptr, int* __restrict__ cursor) {
    __shared__ int sd[256];
    int i = blockIdx.x * 256 + threadIdx.x;
    int c = (i < NN) ? cnt[i] : 0;
    sd[threadIdx.x] = c;
    __syncthreads();
    for (int off = 1; off < 256; off <<= 1) {
        int v = (threadIdx.x >= off) ? sd[threadIdx.x - off] : 0;
        __syncthreads();
        sd[threadIdx.x] += v;
        __syncthreads();
    }
    int excl = bsum[blockIdx.x] + sd[threadIdx.x] - c;
    if (i < NN) { indptr[i] = excl; cursor[i] = excl; }
}

__global__ void fill_kernel(const void* __restrict__ eidx, int* __restrict__ cursor,
                            int* __restrict__ srcs) {
    int e = blockIdx.x * 256 + threadIdx.x;
    int s, d;
    if (edge_is64(eidx)) {
        const long long* q = (const long long*)eidx;
        s = (int)q[e];
        d = (int)q[EE + e];
    } else {
        const int* q = (const int*)eidx;
        s = q[e];
        d = q[EE + e];
    }
    int pos = atomicAdd(&cursor[d], 1);
    srcs[pos] = s;
}

// ---------------- fused [gather | bn-relu] + 64x64 GEMM + col-stats ------------
// GATHER=true : sZ[row] = A[row] + sum_{e in CSR(row)} A[src[e]]   (GIN agg)
// GATHER=false: sZ[row] = relu(bn(A[row]))                          (MLP layer 2)
// then out = sZ @ W + bias, and col sum/sumsq of out accumulated atomically.
template <bool GATHER>
__global__ void __launch_bounds__(256) agg_gemm_kernel(
    const float* __restrict__ A,
    const int* __restrict__ indptr, const int* __restrict__ srcs,
    const float* __restrict__ ssum_in, const float* __restrict__ ssq_in,
    const float* __restrict__ gam, const float* __restrict__ bet,
    const float* __restrict__ W, const float* __restrict__ bias,
    float* __restrict__ out, float* __restrict__ osum, float* __restrict__ osq) {
    extern __shared__ float sm[];
    float* sZ = sm;                         // MTILE * ZSTR
    float* sW = sm + MTILE * ZSTR;          // 64 * 64  (16B-aligned: 16640 floats)
    float* sB = sW + 64 * 64;
    float* sSum = sB + 64;
    float* sSq = sSum + 64;
    float* sS = sSq + 64;
    float* sO = sS + 64;

    const int tid = threadIdx.x;
    {
        float4* sW4 = (float4*)sW;
        const float4* W4 = (const float4*)W;
#pragma unroll
        for (int i = 0; i < 4; i++) sW4[tid + i * 256] = W4[tid + i * 256];
    }
    if (tid < 64) {
        sB[tid] = bias[tid];
        sSum[tid] = 0.f;
        sSq[tid] = 0.f;
        if (!GATHER) {
            float m = ssum_in[tid] * (1.0f / NN);
            float v = ssq_in[tid] * (1.0f / NN) - m * m;
            float s = gam[tid] * rsqrtf(v + BN_EPS);
            sS[tid] = s;
            sO[tid] = bet[tid] - m * s;
        }
    }
    if (!GATHER) __syncthreads();  // phase A reads sS/sO

    // ---- phase A: build sZ (4 passes, 4 threads per row)
    const int rloc0 = tid >> 2;
    const int q = tid & 3;
    const int base = blockIdx.x * MTILE;
#pragma unroll
    for (int p = 0; p < 4; p++) {
        const int rloc = p * 64 + rloc0;
        const int r = base + rloc;
        const bool valid = (r < NN);
        const int rc = valid ? r : NN - 1;
        const float4* a4 = (const float4*)(A + (size_t)rc * 64 + q * 16);
        float4 a0 = a4[0], a1 = a4[1], a2 = a4[2], a3 = a4[3];
        if (GATHER) {
            int e = indptr[rc];
            const int end = valid ? indptr[rc + 1] : e;
            for (; e + 2 <= end; e += 2) {
                int s0 = srcs[e], s1 = srcs[e + 1];
                const float4* p0 = (const float4*)(A + (size_t)s0 * 64 + q * 16);
                const float4* p1 = (const float4*)(A + (size_t)s1 * 64 + q * 16);
                float4 b0 = p0[0], b1 = p0[1], b2 = p0[2], b3 = p0[3];
                float4 c0 = p1[0], c1 = p1[1], c2 = p1[2], c3 = p1[3];
                add4(a0, b0); add4(a0, c0);
                add4(a1, b1); add4(a1, c1);
                add4(a2, b2); add4(a2, c2);
                add4(a3, b3); add4(a3, c3);
            }
            if (e < end) {
                int s0 = srcs[e];
                const float4* p0 = (const float4*)(A + (size_t)s0 * 64 + q * 16);
                add4(a0, p0[0]); add4(a1, p0[1]); add4(a2, p0[2]); add4(a3, p0[3]);
            }
        } else {
            const int k = q * 16;
            a0.x = fmaxf(fmaf(a0.x, sS[k + 0], sO[k + 0]), 0.f);
            a0.y = fmaxf(fmaf(a0.y, sS[k + 1], sO[k + 1]), 0.f);
            a0.z = fmaxf(fmaf(a0.z, sS[k + 2], sO[k + 2]), 0.f);
            a0.w = fmaxf(fmaf(a0.w, sS[k + 3], sO[k + 3]), 0.f);
            a1.x = fmaxf(fmaf(a1.x, sS[k + 4], sO[k + 4]), 0.f);
            a1.y = fmaxf(fmaf(a1.y, sS[k + 5], sO[k + 5]), 0.f);
            a1.z = fmaxf(fmaf(a1.z, sS[k + 6], sO[k + 6]), 0.f);
            a1.w = fmaxf(fmaf(a1.w, sS[k + 7], sO[k + 7]), 0.f);
            a2.x = fmaxf(fmaf(a2.x, sS[k + 8], sO[k + 8]), 0.f);
            a2.y = fmaxf(fmaf(a2.y, sS[k + 9], sO[k + 9]), 0.f);
            a2.z = fmaxf(fmaf(a2.z, sS[k + 10], sO[k + 10]), 0.f);
            a2.w = fmaxf(fmaf(a2.w, sS[k + 11], sO[k + 11]), 0.f);
            a3.x = fmaxf(fmaf(a3.x, sS[k + 12], sO[k + 12]), 0.f);
            a3.y = fmaxf(fmaf(a3.y, sS[k + 13], sO[k + 13]), 0.f);
            a3.z = fmaxf(fmaf(a3.z, sS[k + 14], sO[k + 14]), 0.f);
            a3.w = fmaxf(fmaf(a3.w, sS[k + 15], sO[k + 15]), 0.f);
        }
        float* zr = sZ + rloc * ZSTR + q * 16;
        zr[0] = a0.x; zr[1] = a0.y; zr[2] = a0.z; zr[3] = a0.w;
        zr[4] = a1.x; zr[5] = a1.y; zr[6] = a1.z; zr[7] = a1.w;
        zr[8] = a2.x; zr[9] = a2.y; zr[10] = a2.z; zr[11] = a2.w;
        zr[12] = a3.x; zr[13] = a3.y; zr[14] = a3.z; zr[15] = a3.w;
    }
    __syncthreads();

    // ---- phase B: GEMM, thread = 8 rows x 8 cols
    const int rg = tid >> 3;   // 0..31
    const int cg = tid & 7;    // 0..7
    const int j0 = cg * 8;
    float acc[8][8];
#pragma unroll
    for (int i = 0; i < 8; i++)
#pragma unroll
        for (int j = 0; j < 8; j++) acc[i][j] = sB[j0 + j];

#pragma unroll 4
    for (int k = 0; k < 64; k++) {
        float zv[8];
#pragma unroll
        for (int i = 0; i < 8; i++) zv[i] = sZ[(rg * 8 + i) * ZSTR + k];
        float4 w0 = *(const float4*)(sW + k * 64 + j0);
        float4 w1 = *(const float4*)(sW + k * 64 + j0 + 4);
        float wv[8] = {w0.x, w0.y, w0.z, w0.w, w1.x, w1.y, w1.z, w1.w};
#pragma unroll
        for (int i = 0; i < 8; i++)
#pragma unroll
            for (int j = 0; j < 8; j++)
                acc[i][j] = fmaf(zv[i], wv[j], acc[i][j]);
    }

    // ---- store + column stats
    float csum[8], csq[8];
#pragma unroll
    for (int j = 0; j < 8; j++) { csum[j] = 0.f; csq[j] = 0.f; }
#pragma unroll
    for (int i = 0; i < 8; i++) {
        const int r = base + rg * 8 + i;
        if (r < NN) {
            float4 o0 = make_float4(acc[i][0], acc[i][1], acc[i][2], acc[i][3]);
            float4 o1 = make_float4(acc[i][4], acc[i][5], acc[i][6], acc[i][7]);
            *(float4*)(out + (size_t)r * 64 + j0) = o0;
            *(float4*)(out + (size_t)r * 64 + j0 + 4) = o1;
#pragma unroll
            for (int j = 0; j < 8; j++) {
                csum[j] += acc[i][j];
                csq[j] += acc[i][j] * acc[i][j];
            }
        }
    }
#pragma unroll
    for (int j = 0; j < 8; j++) {
        csum[j] += __shfl_down_sync(0xffffffffu, csum[j], 8);
        csq[j] += __shfl_down_sync(0xffffffffu, csq[j], 8);
        csum[j] += __shfl_down_sync(0xffffffffu, csum[j], 16);
        csq[j] += __shfl_down_sync(0xffffffffu, csq[j], 16);
    }
    if ((tid & 31) < 8) {
#pragma unroll
        for (int j = 0; j < 8; j++) {
            atomicAdd(&sSum[j0 + j], csum[j]);
            atomicAdd(&sSq[j0 + j], csq[j]);
        }
    }
    __syncthreads();
    if (tid < 64) {
        atomicAdd(&osum[tid], sSum[tid]);
        atomicAdd(&osq[tid], sSq[tid]);
    }
}

// ---------------- fused (bn+relu) + parallel pooling --------------------------
template <bool BN>
__global__ void bnpool_kernel(const float* __restrict__ X,
                              const float* __restrict__ ssum,
                              const float* __restrict__ ssq,
                              const float* __restrict__ gam,
                              const float* __restrict__ bet,
                              const void* __restrict__ batch,
                              float* __restrict__ hout,
                              float* __restrict__ pooled) {
    __shared__ float sS[64], sO[64];
    const int tid = threadIdx.x;
    if (BN) {
        if (tid < 64) {
            float m = ssum[tid] * (1.0f / NN);
            float v = ssq[tid] * (1.0f / NN) - m * m;
            float s = gam[tid] * rsqrtf(v + BN_EPS);
            sS[tid] = s;
            sO[tid] = bet[tid] - m * s;
        }
        __syncthreads();
    }
    long i = (long)blockIdx.x * 256 + tid;   // grid exact: NN*16/256
    const int row = (int)(i >> 4);
    const int k = (int)(i & 15) * 4;
    float4 v = ((const float4*)X)[i];
    if (BN) {
        v.x = fmaxf(fmaf(v.x, sS[k + 0], sO[k + 0]), 0.f);
        v.y = fmaxf(fmaf(v.y, sS[k + 1], sO[k + 1]), 0.f);
        v.z = fmaxf(fmaf(v.z, sS[k + 2], sO[k + 2]), 0.f);
        v.w = fmaxf(fmaf(v.w, sS[k + 3], sO[k + 3]), 0.f);
        ((float4*)hout)[i] = v;
    }
    int g = batch_is64(batch) ? (int)((const long long*)batch)[row]
                              : ((const int*)batch)[row];
    float* basep = pooled + (size_t)g * 64 + k;
    asm volatile("red.global.add.v4.f32 [%0], {%1,%2,%3,%4};"
                 :: "l"(basep), "f"(v.x), "f"(v.y), "f"(v.z), "f"(v.w)
                 : "memory");
}

// ---------------- final jumping-knowledge readout -------------------------------
__global__ void readout_kernel(const float* __restrict__ w0, const float* __restrict__ b0,
                               const float* __restrict__ w1, const float* __restrict__ b1,
                               const float* __restrict__ w2, const float* __restrict__ b2,
                               float* __restrict__ out) {
    int t = blockIdx.x * blockDim.x + threadIdx.x;
    if (t >= GG * CC) return;
    int g = t / CC, c = t % CC;
    float acc = b0[c] + b1[c] + b2[c];
    const float* p0 = g_pooled + (size_t)g * 64;
    const float* p1 = g_pooled + (size_t)GG * 64 + (size_t)g * 64;
    const float* p2 = g_pooled + (size_t)2 * GG * 64 + (size_t)g * 64;
#pragma unroll
    for (int f = 0; f < 64; f++) {
        acc = fmaf(p0[f], w0[f * CC + c], acc);
        acc = fmaf(p1[f], w1[f * CC + c], acc);
        acc = fmaf(p2[f], w2[f * CC + c], acc);
    }
    out[t] = acc;
}

// ---------------- launch --------------------------------------------------------
extern "C" void kernel_launch(void* const* d_in, const int* in_sizes, int n_in,
                              void* d_out, int out_size) {
    const float* x = (const float*)d_in[0];
    const void* eidx = d_in[1];
    const void* batch = d_in[2];

    void *tp, *up, *h1p, *h2p, *statp, *pooledp;
    void *cntp, *indp, *curp, *srcp, *bsump;
    cudaGetSymbolAddress(&tp, g_t);
    cudaGetSymbolAddress(&up, g_u);
    cudaGetSymbolAddress(&h1p, g_h1);
    cudaGetSymbolAddress(&h2p, g_h2);
    cudaGetSymbolAddress(&statp, g_stat);
    cudaGetSymbolAddress(&pooledp, g_pooled);
    cudaGetSymbolAddress(&cntp, g_cnt);
    cudaGetSymbolAddress(&indp, g_indptr);
    cudaGetSymbolAddress(&curp, g_cursor);
    cudaGetSymbolAddress(&srcp, g_srcs);
    cudaGetSymbolAddress(&bsump, g_bsum);

    float* t = (float*)tp;
    float* u = (float*)up;
    float* stat = (float*)statp;
    float* pooled = (float*)pooledp;
    float* houts[2] = {(float*)h1p, (float*)h2p};
    int* cnt = (int*)cntp;
    int* indptr = (int*)indp;
    int* cursor = (int*)curp;
    int* srcs = (int*)srcp;
    int* bsum = (int*)bsump;

    const int EDGE_BLOCKS = EE / 256;            // 6250
    const int FUSE_BLOCKS = (NN + MTILE - 1) / MTILE;  // 391
    const int ELEM_BLOCKS = NN * 16 / 256;       // 6250
    const int INIT_BLOCKS = (3 * GG * HH + 255) / 256; // 750

    const int SMEM_BYTES = (MTILE * ZSTR + 64 * 64 + 64 * 5) * sizeof(float);
    static bool attr_set = false;
    if (!attr_set) {
        cudaFuncSetAttribute(agg_gemm_kernel<true>,
                             cudaFuncAttributeMaxDynamicSharedMemorySize, SMEM_BYTES);
        cudaFuncSetAttribute(agg_gemm_kernel<false>,
                             cudaFuncAttributeMaxDynamicSharedMemorySize, SMEM_BYTES);
        attr_set = true;
    }

    // 1: init
    init_kernel<<<INIT_BLOCKS, 256>>>(cnt, stat, pooled);
    // 2-6: CSR build
    count_kernel<<<EDGE_BLOCKS, 256>>>(eidx, cnt);
    scanA_kernel<<<SCAN_BLOCKS, 256>>>(cnt, bsum);
    scanB_kernel<<<1, 32>>>(bsum, indptr);
    scanC_kernel<<<SCAN_BLOCKS, 256>>>(cnt, bsum, indptr, cursor);
    fill_kernel<<<EDGE_BLOCKS, 256>>>(eidx, cursor, srcs);

    const float* hin = x;
    for (int l = 0; l < 2; l++) {
        const int b = 3 + l * 8;
        const float* w1  = (const float*)d_in[b + 0];
        const float* b1  = (const float*)d_in[b + 1];
        const float* g1  = (const float*)d_in[b + 2];
        const float* be1 = (const float*)d_in[b + 3];
        const float* w2  = (const float*)d_in[b + 4];
        const float* b2  = (const float*)d_in[b + 5];
        const float* bng = (const float*)d_in[b + 6];
        const float* bnb = (const float*)d_in[b + 7];
        float* hout = houts[l];
        float* st = stat + l * 256;

        // 7 (layer 0): gather + GEMM1 + stats(t)      <- profiled launch
        agg_gemm_kernel<true><<<FUSE_BLOCKS, 256, SMEM_BYTES>>>(
            hin, indptr, srcs, nullptr, nullptr, nullptr, nullptr,
            w1, b1, t, st, st + 64);

        // bn(t)+relu fused into GEMM2 tile load; u = ... @ w2 + b2; stats(u)
        agg_gemm_kernel<false><<<FUSE_BLOCKS, 256, SMEM_BYTES>>>(
            t, nullptr, nullptr, st, st + 64, g1, be1,
            w2, b2, u, st + 128, st + 192);

        // h_next = relu(bn(u)); pooled[l+1] += rows
        bnpool_kernel<true><<<ELEM_BLOCKS, 256>>>(
            u, st + 128, st + 192, bng, bnb, batch, hout,
            pooled + (size_t)(l + 1) * GG * HH);

        hin = hout;
    }

    // layer-0 pooling of raw x
    bnpool_kernel<false><<<ELEM_BLOCKS, 256>>>(
        x, nullptr, nullptr, nullptr, nullptr, batch, nullptr, pooled);

    readout_kernel<<<(GG * CC + 255) / 256, 256>>>(
        (const float*)d_in[19], (const float*)d_in[20],
        (const float*)d_in[21], (const float*)d_in[22],
        (const float*)d_in[23], (const float*)d_in[24],
        (float*)d_out);
}

// round 4
// speedup vs baseline: 3.1396x; 1.0169x over previous
#include <cuda_runtime.h>
#include <cstdint>

#define NN 100000
#define EE 1600000
#define HH 64
#define CC 10
#define GG 1000
#define BN_EPS 1e-5f
#define MTILE 256
#define ZSTR 65   // smem z row stride (conflict-free scalar reads)

// ---------------- scratch (static device globals) ---------------------------
__device__ float g_t[NN * HH];
__device__ float g_u0[NN * HH];
__device__ float g_u1[NN * HH];
__device__ float g_stat[8 * 64];
__device__ float g_pooled[3 * GG * HH];
__device__ int   g_cnt[NN];
__device__ int   g_indptr[NN + 1];
__device__ int   g_cursor[NN];
__device__ int   g_srcs[EE];
__device__ int   g_bsum[512];

#define SCAN_BLOCKS 391   // ceil(100000/256)

// ---------------- index-width detection --------------------------------------
__device__ __forceinline__ bool edge_is64(const void* p) {
    const int* q = (const int*)p;
    return (q[1] | q[3] | q[5] | q[7]) == 0;
}
__device__ __forceinline__ bool batch_is64(const void* p) {
    const int* q = (const int*)p;
    return (q[NN - 1] | q[NN - 3] | q[NN - 5] | q[NN - 7]) == 0;
}

__device__ __forceinline__ void add4(float4& a, const float4 b) {
    a.x += b.x; a.y += b.y; a.z += b.z; a.w += b.w;
}
// v = relu(v * s + o), componentwise
__device__ __forceinline__ float4 bn4(float4 v, const float4 s, const float4 o) {
    v.x = fmaxf(fmaf(v.x, s.x, o.x), 0.f);
    v.y = fmaxf(fmaf(v.y, s.y, o.y), 0.f);
    v.z = fmaxf(fmaf(v.z, s.z, o.z), 0.f);
    v.w = fmaxf(fmaf(v.w, s.w, o.w), 0.f);
    return v;
}

// ---------------- init: zero cnt / stat / pooled ------------------------------
__global__ void init_kernel(int* __restrict__ cnt, float* __restrict__ stat,
                            float* __restrict__ pooled) {
    int i = blockIdx.x * 256 + threadIdx.x;
    if (i < NN) cnt[i] = 0;
    if (i < 8 * 64) stat[i] = 0.f;
    if (i < 3 * GG * HH) pooled[i] = 0.f;
}

// ---------------- CSR build ----------------------------------------------------
__global__ void count_kernel(const void* __restrict__ eidx, int* __restrict__ cnt) {
    int e = blockIdx.x * 256 + threadIdx.x;
    int d = edge_is64(eidx) ? (int)((const long long*)eidx)[EE + e]
                            : ((const int*)eidx)[EE + e];
    atomicAdd(&cnt[d], 1);
}

__global__ void scanA_kernel(const int* __restrict__ cnt, int* __restrict__ bsum) {
    __shared__ int sd[256];
    int i = blockIdx.x * 256 + threadIdx.x;
    sd[threadIdx.x] = (i < NN) ? cnt[i] : 0;
    __syncthreads();
    for (int off = 128; off > 0; off >>= 1) {
        if (threadIdx.x < off) sd[threadIdx.x] += sd[threadIdx.x + off];
        __syncthreads();
    }
    if (threadIdx.x == 0) bsum[blockIdx.x] = sd[0];
}

// parallel exclusive scan of the 391 block sums (single 512-thread block)
__global__ void scanB_kernel(int* __restrict__ bsum, int* __restrict__ indptr) {
    __shared__ int sd[512];
    const int tid = threadIdx.x;
    int v = (tid < SCAN_BLOCKS) ? bsum[tid] : 0;
    sd[tid] = v;
    __syncthreads();
    for (int off = 1; off < 512; off <<= 1) {
        int t = (tid >= off) ? sd[tid - off] : 0;
        __syncthreads();
        sd[tid] += t;
        __syncthreads();
    }
    if (tid < SCAN_BLOCKS) bsum[tid] = sd[tid] - v;   // exclusive
    if (tid == 0) indptr[NN] = EE;
}

__global__ void scanC_kernel(const int* __restrict__ cnt, const int* __restrict__ bsum,
                             int* __restrict__ indptr, int* __restrict__ cursor) {
    __shared__ int sd[256];
    int i = blockIdx.x * 256 + threadIdx.x;
    int c = (i < NN) ? cnt[i] : 0;
    sd[threadIdx.x] = c;
    __syncthreads();
    for (int off = 1; off < 256; off <<= 1) {
        int v = (threadIdx.x >= off) ? sd[threadIdx.x - off] : 0;
        __syncthreads();
        sd[threadIdx.x] += v;
        __syncthreads();
    }
    int excl = bsum[blockIdx.x] + sd[threadIdx.x] - c;
    if (i < NN) { indptr[i] = excl; cursor[i] = excl; }
}

__global__ void fill_kernel(const void* __restrict__ eidx, int* __restrict__ cursor,
                            int* __restrict__ srcs) {
    int e = blockIdx.x * 256 + threadIdx.x;
    int s, d;
    if (edge_is64(eidx)) {
        const long long* q = (const long long*)eidx;
        s = (int)q[e];
        d = (int)q[EE + e];
    } else {
        const int* q = (const int*)eidx;
        s = q[e];
        d = q[EE + e];
    }
    int pos = atomicAdd(&cursor[d], 1);
    srcs[pos] = s;
}

// ---------------- fused [gather] [bn-relu] + 64x64 GEMM + col-stats ------------
// row transform f(.) = BNIN ? relu(bn(.)) : identity   (bn from ssum/ssq + gam/bet)
// GATHER=true : sZ[row] = f(A[row]) + sum_{e in CSR(row)} f(A[src[e]])
// GATHER=false: sZ[row] = f(A[row])
// then out = sZ @ W + bias; col sum/sumsq of out accumulated into osum/osq.
template <bool GATHER, bool BNIN>
__global__ void __launch_bounds__(256) agg_gemm_kernel(
    const float* __restrict__ A,
    const int* __restrict__ indptr, const int* __restrict__ srcs,
    const float* __restrict__ ssum_in, const float* __restrict__ ssq_in,
    const float* __restrict__ gam, const float* __restrict__ bet,
    const float* __restrict__ W, const float* __restrict__ bias,
    float* __restrict__ out, float* __restrict__ osum, float* __restrict__ osq) {
    extern __shared__ float sm[];
    float* sZ = sm;                         // MTILE * ZSTR
    float* sW = sm + MTILE * ZSTR;          // 64 * 64
    float* sB = sW + 64 * 64;
    float* sSum = sB + 64;
    float* sSq = sSum + 64;
    float* sS = sSq + 64;
    float* sO = sS + 64;

    const int tid = threadIdx.x;
    {
        float4* sW4 = (float4*)sW;
        const float4* W4 = (const float4*)W;
#pragma unroll
        for (int i = 0; i < 4; i++) sW4[tid + i * 256] = W4[tid + i * 256];
    }
    if (tid < 64) {
        sB[tid] = bias[tid];
        sSum[tid] = 0.f;
        sSq[tid] = 0.f;
        if (BNIN) {
            float m = ssum_in[tid] * (1.0f / NN);
            float v = ssq_in[tid] * (1.0f / NN) - m * m;
            float s = gam[tid] * rsqrtf(v + BN_EPS);
            sS[tid] = s;
            sO[tid] = bet[tid] - m * s;
        }
    }
    if (BNIN) __syncthreads();  // phase A reads sS/sO

    // ---- phase A: build sZ (4 passes, 4 threads per row; thread owns quarter q)
    const int rloc0 = tid >> 2;
    const int q = tid & 3;
    const int base = blockIdx.x * MTILE;

    float4 ss0, ss1, ss2, ss3, oo0, oo1, oo2, oo3;
    if (BNIN) {
        const float4* s4 = (const float4*)(sS + q * 16);
        const float4* o4 = (const float4*)(sO + q * 16);
        ss0 = s4[0]; ss1 = s4[1]; ss2 = s4[2]; ss3 = s4[3];
        oo0 = o4[0]; oo1 = o4[1]; oo2 = o4[2]; oo3 = o4[3];
    }

#pragma unroll
    for (int p = 0; p < 4; p++) {
        const int rloc = p * 64 + rloc0;
        const int r = base + rloc;
        const bool valid = (r < NN);
        const int rc = valid ? r : NN - 1;
        const float4* a4 = (const float4*)(A + (size_t)rc * 64 + q * 16);
        float4 a0 = a4[0], a1 = a4[1], a2 = a4[2], a3 = a4[3];
        if (BNIN) {
            a0 = bn4(a0, ss0, oo0); a1 = bn4(a1, ss1, oo1);
            a2 = bn4(a2, ss2, oo2); a3 = bn4(a3, ss3, oo3);
        }
        if (GATHER) {
            int e = indptr[rc];
            const int end = valid ? indptr[rc + 1] : e;
            for (; e + 2 <= end; e += 2) {
                int s0 = srcs[e], s1 = srcs[e + 1];
                const float4* p0 = (const float4*)(A + (size_t)s0 * 64 + q * 16);
                const float4* p1 = (const float4*)(A + (size_t)s1 * 64 + q * 16);
                float4 b0 = p0[0], b1 = p0[1], b2 = p0[2], b3 = p0[3];
                float4 c0 = p1[0], c1 = p1[1], c2 = p1[2], c3 = p1[3];
                if (BNIN) {
                    b0 = bn4(b0, ss0, oo0); b1 = bn4(b1, ss1, oo1);
                    b2 = bn4(b2, ss2, oo2); b3 = bn4(b3, ss3, oo3);
                    c0 = bn4(c0, ss0, oo0); c1 = bn4(c1, ss1, oo1);
                    c2 = bn4(c2, ss2, oo2); c3 = bn4(c3, ss3, oo3);
                }
                add4(a0, b0); add4(a0, c0);
                add4(a1, b1); add4(a1, c1);
                add4(a2, b2); add4(a2, c2);
                add4(a3, b3); add4(a3, c3);
            }
            if (e < end) {
                int s0 = srcs[e];
                const float4* p0 = (const float4*)(A + (size_t)s0 * 64 + q * 16);
                float4 b0 = p0[0], b1 = p0[1], b2 = p0[2], b3 = p0[3];
                if (BNIN) {
                    b0 = bn4(b0, ss0, oo0); b1 = bn4(b1, ss1, oo1);
                    b2 = bn4(b2, ss2, oo2); b3 = bn4(b3, ss3, oo3);
                }
                add4(a0, b0); add4(a1, b1); add4(a2, b2); add4(a3, b3);
            }
        }
        float* zr = sZ + rloc * ZSTR + q * 16;
        zr[0] = a0.x; zr[1] = a0.y; zr[2] = a0.z; zr[3] = a0.w;
        zr[4] = a1.x; zr[5] = a1.y; zr[6] = a1.z; zr[7] = a1.w;
        zr[8] = a2.x; zr[9] = a2.y; zr[10] = a2.z; zr[11] = a2.w;
        zr[12] = a3.x; zr[13] = a3.y; zr[14] = a3.z; zr[15] = a3.w;
    }
    __syncthreads();

    // ---- phase B: GEMM, thread = 8 rows x 8 cols
    const int rg = tid >> 3;   // 0..31
    const int cg = tid & 7;    // 0..7
    const int j0 = cg * 8;
    float acc[8][8];
#pragma unroll
    for (int i = 0; i < 8; i++)
#pragma unroll
        for (int j = 0; j < 8; j++) acc[i][j] = sB[j0 + j];

#pragma unroll 4
    for (int k = 0; k < 64; k++) {
        float zv[8];
#pragma unroll
        for (int i = 0; i < 8; i++) zv[i] = sZ[(rg * 8 + i) * ZSTR + k];
        float4 w0 = *(const float4*)(sW + k * 64 + j0);
        float4 w1 = *(const float4*)(sW + k * 64 + j0 + 4);
        float wv[8] = {w0.x, w0.y, w0.z, w0.w, w1.x, w1.y, w1.z, w1.w};
#pragma unroll
        for (int i = 0; i < 8; i++)
#pragma unroll
            for (int j = 0; j < 8; j++)
                acc[i][j] = fmaf(zv[i], wv[j], acc[i][j]);
    }

    // ---- store + column stats
    float csum[8], csq[8];
#pragma unroll
    for (int j = 0; j < 8; j++) { csum[j] = 0.f; csq[j] = 0.f; }
#pragma unroll
    for (int i = 0; i < 8; i++) {
        const int r = base + rg * 8 + i;
        if (r < NN) {
            float4 o0 = make_float4(acc[i][0], acc[i][1], acc[i][2], acc[i][3]);
            float4 o1 = make_float4(acc[i][4], acc[i][5], acc[i][6], acc[i][7]);
            *(float4*)(out + (size_t)r * 64 + j0) = o0;
            *(float4*)(out + (size_t)r * 64 + j0 + 4) = o1;
#pragma unroll
            for (int j = 0; j < 8; j++) {
                csum[j] += acc[i][j];
                csq[j] += acc[i][j] * acc[i][j];
            }
        }
    }
#pragma unroll
    for (int j = 0; j < 8; j++) {
        csum[j] += __shfl_down_sync(0xffffffffu, csum[j], 8);
        csq[j] += __shfl_down_sync(0xffffffffu, csq[j], 8);
        csum[j] += __shfl_down_sync(0xffffffffu, csum[j], 16);
        csq[j] += __shfl_down_sync(0xffffffffu, csq[j], 16);
    }
    if ((tid & 31) < 8) {
#pragma unroll
        for (int j = 0; j < 8; j++) {
            atomicAdd(&sSum[j0 + j], csum[j]);
            atomicAdd(&sSq[j0 + j], csq[j]);
        }
    }
    __syncthreads();
    if (tid < 64) {
        atomicAdd(&osum[tid], sSum[tid]);
        atomicAdd(&osq[tid], sSq[tid]);
    }
}

// ---------------- pooling, optional on-the-fly bn+relu ------------------------
// pooled[batch[row]] += (BN ? relu(bn(X[row])) : X[row])
template <bool BN>
__global__ void poolbn_kernel(const float* __restrict__ X,
                              const float* __restrict__ ssum,
                              const float* __restrict__ ssq,
                              const float* __restrict__ gam,
                              const float* __restrict__ bet,
                              const void* __restrict__ batch,
                              float* __restrict__ pooled) {
    __shared__ float sS[64], sO[64];
    const int tid = threadIdx.x;
    if (BN) {
        if (tid < 64) {
            float m = ssum[tid] * (1.0f / NN);
            float v = ssq[tid] * (1.0f / NN) - m * m;
            float s = gam[tid] * rsqrtf(v + BN_EPS);
            sS[tid] = s;
            sO[tid] = bet[tid] - m * s;
        }
        __syncthreads();
    }
    long i = (long)blockIdx.x * 256 + tid;   // grid exact: NN*16/256
    const int row = (int)(i >> 4);
    const int k = (int)(i & 15) * 4;
    float4 v = ((const float4*)X)[i];
    if (BN) {
        v.x = fmaxf(fmaf(v.x, sS[k + 0], sO[k + 0]), 0.f);
        v.y = fmaxf(fmaf(v.y, sS[k + 1], sO[k + 1]), 0.f);
        v.z = fmaxf(fmaf(v.z, sS[k + 2], sO[k + 2]), 0.f);
        v.w = fmaxf(fmaf(v.w, sS[k + 3], sO[k + 3]), 0.f);
    }
    int g = batch_is64(batch) ? (int)((const long long*)batch)[row]
                              : ((const int*)batch)[row];
    float* basep = pooled + (size_t)g * 64 + k;
    asm volatile("red.global.add.v4.f32 [%0], {%1,%2,%3,%4};"
                 :: "l"(basep), "f"(v.x), "f"(v.y), "f"(v.z), "f"(v.w)
                 : "memory");
}

// ---------------- final jumping-knowledge readout -------------------------------
__global__ void readout_kernel(const float* __restrict__ w0, const float* __restrict__ b0,
                               const float* __restrict__ w1, const float* __restrict__ b1,
                               const float* __restrict__ w2, const float* __restrict__ b2,
                               float* __restrict__ out) {
    int t = blockIdx.x * blockDim.x + threadIdx.x;
    if (t >= GG * CC) return;
    int g = t / CC, c = t % CC;
    float acc = b0[c] + b1[c] + b2[c];
    const float* p0 = g_pooled + (size_t)g * 64;
    const float* p1 = g_pooled + (size_t)GG * 64 + (size_t)g * 64;
    const float* p2 = g_pooled + (size_t)2 * GG * 64 + (size_t)g * 64;
#pragma unroll
    for (int f = 0; f < 64; f++) {
        acc = fmaf(p0[f], w0[f * CC + c], acc);
        acc = fmaf(p1[f], w1[f * CC + c], acc);
        acc = fmaf(p2[f], w2[f * CC + c], acc);
    }
    out[t] = acc;
}

// ---------------- launch --------------------------------------------------------
extern "C" void kernel_launch(void* const* d_in, const int* in_sizes, int n_in,
                              void* d_out, int out_size) {
    const float* x = (const float*)d_in[0];
    const void* eidx = d_in[1];
    const void* batch = d_in[2];

    void *tp, *u0p, *u1p, *statp, *pooledp;
    void *cntp, *indp, *curp, *srcp, *bsump;
    cudaGetSymbolAddress(&tp, g_t);
    cudaGetSymbolAddress(&u0p, g_u0);
    cudaGetSymbolAddress(&u1p, g_u1);
    cudaGetSymbolAddress(&statp, g_stat);
    cudaGetSymbolAddress(&pooledp, g_pooled);
    cudaGetSymbolAddress(&cntp, g_cnt);
    cudaGetSymbolAddress(&indp, g_indptr);
    cudaGetSymbolAddress(&curp, g_cursor);
    cudaGetSymbolAddress(&srcp, g_srcs);
    cudaGetSymbolAddress(&bsump, g_bsum);

    float* t = (float*)tp;
    float* u0 = (float*)u0p;
    float* u1 = (float*)u1p;
    float* stat = (float*)statp;
    float* pooled = (float*)pooledp;
    int* cnt = (int*)cntp;
    int* indptr = (int*)indp;
    int* cursor = (int*)curp;
    int* srcs = (int*)srcp;
    int* bsum = (int*)bsump;

    const int EDGE_BLOCKS = EE / 256;                   // 6250
    const int FUSE_BLOCKS = (NN + MTILE - 1) / MTILE;   // 391
    const int ELEM_BLOCKS = NN * 16 / 256;              // 6250
    const int INIT_BLOCKS = (3 * GG * HH + 255) / 256;  // 750

    const int SMEM_BYTES = (MTILE * ZSTR + 64 * 64 + 64 * 5) * sizeof(float);
    static bool attr_set = false;
    if (!attr_set) {
        cudaFuncSetAttribute(agg_gemm_kernel<true, false>,
                             cudaFuncAttributeMaxDynamicSharedMemorySize, SMEM_BYTES);
        cudaFuncSetAttribute(agg_gemm_kernel<true, true>,
                             cudaFuncAttributeMaxDynamicSharedMemorySize, SMEM_BYTES);
        cudaFuncSetAttribute(agg_gemm_kernel<false, true>,
                             cudaFuncAttributeMaxDynamicSharedMemorySize, SMEM_BYTES);
        attr_set = true;
    }

    // CSR build
    init_kernel<<<INIT_BLOCKS, 256>>>(cnt, stat, pooled);
    count_kernel<<<EDGE_BLOCKS, 256>>>(eidx, cnt);
    scanA_kernel<<<SCAN_BLOCKS, 256>>>(cnt, bsum);
    scanB_kernel<<<1, 512>>>(bsum, indptr);
    scanC_kernel<<<SCAN_BLOCKS, 256>>>(cnt, bsum, indptr, cursor);
    fill_kernel<<<EDGE_BLOCKS, 256>>>(eidx, cursor, srcs);

    const float* w1_0  = (const float*)d_in[3];
    const float* b1_0  = (const float*)d_in[4];
    const float* g1_0  = (const float*)d_in[5];
    const float* be1_0 = (const float*)d_in[6];
    const float* w2_0  = (const float*)d_in[7];
    const float* b2_0  = (const float*)d_in[8];
    const float* bng0  = (const float*)d_in[9];
    const float* bnb0  = (const float*)d_in[10];
    const float* w1_1  = (const float*)d_in[11];
    const float* b1_1  = (const float*)d_in[12];
    const float* g1_1  = (const float*)d_in[13];
    const float* be1_1 = (const float*)d_in[14];
    const float* w2_1  = (const float*)d_in[15];
    const float* b2_1  = (const float*)d_in[16];
    const float* bng1  = (const float*)d_in[17];
    const float* bnb1  = (const float*)d_in[18];

    float* st0 = stat;         // t0 sum/sq @0/64, u0 sum/sq @128/192
    float* st1 = stat + 256;   // t1 sum/sq @0/64, u1 sum/sq @128/192

    // ---- layer 0
    agg_gemm_kernel<true, false><<<FUSE_BLOCKS, 256, SMEM_BYTES>>>(
        x, indptr, srcs, nullptr, nullptr, nullptr, nullptr,
        w1_0, b1_0, t, st0, st0 + 64);
    agg_gemm_kernel<false, true><<<FUSE_BLOCKS, 256, SMEM_BYTES>>>(
        t, nullptr, nullptr, st0, st0 + 64, g1_0, be1_0,
        w2_0, b2_0, u0, st0 + 128, st0 + 192);
    poolbn_kernel<true><<<ELEM_BLOCKS, 256>>>(
        u0, st0 + 128, st0 + 192, bng0, bnb0, batch, pooled + (size_t)GG * HH);

    // ---- layer 1 (h1 = relu(bn(u0)) materialized nowhere: bn fused into gather)
    agg_gemm_kernel<true, true><<<FUSE_BLOCKS, 256, SMEM_BYTES>>>(
        u0, indptr, srcs, st0 + 128, st0 + 192, bng0, bnb0,
        w1_1, b1_1, t, st1, st1 + 64);
    agg_gemm_kernel<false, true><<<FUSE_BLOCKS, 256, SMEM_BYTES>>>(
        t, nullptr, nullptr, st1, st1 + 64, g1_1, be1_1,
        w2_1, b2_1, u1, st1 + 128, st1 + 192);
    poolbn_kernel<true><<<ELEM_BLOCKS, 256>>>(
        u1, st1 + 128, st1 + 192, bng1, bnb1, batch, pooled + (size_t)2 * GG * HH);

    // layer-0 pooling of raw x
    poolbn_kernel<false><<<ELEM_BLOCKS, 256>>>(
        x, nullptr, nullptr, nullptr, nullptr, batch, pooled);

    readout_kernel<<<(GG * CC + 255) / 256, 256>>>(
        (const float*)d_in[19], (const float*)d_in[20],
        (const float*)d_in[21], (const float*)d_in[22],
        (const float*)d_in[23], (const float*)d_in[24],
        (float*)d_out);
}

// round 5
// speedup vs baseline: 3.5699x; 1.1371x over previous
#include <cuda_runtime.h>
#include <cstdint>

#define NN 100000
#define EE 1600000
#define HH 64
#define CC 10
#define GG 1000
#define BN_EPS 1e-5f
#define MTILE 128
#define ZSTR 65

// ---------------- scratch (static device globals) ---------------------------
__device__ float g_t[NN * HH];
__device__ float g_u0[NN * HH];
__device__ float g_u1[NN * HH];
__device__ float g_stat[8 * 64];
__device__ float g_pooled[3 * GG * HH];
__device__ int   g_cnt[NN];
__device__ int   g_indptr[NN + 1];
__device__ int   g_cursor[NN];
__device__ int   g_srcs[EE];
__device__ int   g_bsum[512];

#define SCAN_BLOCKS 391   // ceil(100000/256)

// ---------------- index-width detection --------------------------------------
__device__ __forceinline__ bool edge_is64(const void* p) {
    const int* q = (const int*)p;
    return (q[1] | q[3] | q[5] | q[7]) == 0;
}
__device__ __forceinline__ bool batch_is64(const void* p) {
    const int* q = (const int*)p;
    return (q[NN - 1] | q[NN - 3] | q[NN - 5] | q[NN - 7]) == 0;
}

__device__ __forceinline__ float2 bn2(float2 v, const float2 s, const float2 o) {
    v.x = fmaxf(fmaf(v.x, s.x, o.x), 0.f);
    v.y = fmaxf(fmaf(v.y, s.y, o.y), 0.f);
    return v;
}

// ---------------- init: zero cnt / stat / pooled ------------------------------
__global__ void init_kernel(int* __restrict__ cnt, float* __restrict__ stat,
                            float* __restrict__ pooled) {
    int i = blockIdx.x * 256 + threadIdx.x;
    if (i < NN) cnt[i] = 0;
    if (i < 8 * 64) stat[i] = 0.f;
    if (i < 3 * GG * HH) pooled[i] = 0.f;
}

// ---------------- CSR build ----------------------------------------------------
__global__ void count_kernel(const void* __restrict__ eidx, int* __restrict__ cnt) {
    int e = blockIdx.x * 256 + threadIdx.x;
    int d = edge_is64(eidx) ? (int)((const long long*)eidx)[EE + e]
                            : ((const int*)eidx)[EE + e];
    atomicAdd(&cnt[d], 1);
}

__global__ void scanA_kernel(const int* __restrict__ cnt, int* __restrict__ bsum) {
    __shared__ int sd[256];
    int i = blockIdx.x * 256 + threadIdx.x;
    sd[threadIdx.x] = (i < NN) ? cnt[i] : 0;
    __syncthreads();
    for (int off = 128; off > 0; off >>= 1) {
        if (threadIdx.x < off) sd[threadIdx.x] += sd[threadIdx.x + off];
        __syncthreads();
    }
    if (threadIdx.x == 0) bsum[blockIdx.x] = sd[0];
}

__global__ void scanB_kernel(int* __restrict__ bsum, int* __restrict__ indptr) {
    __shared__ int sd[512];
    const int tid = threadIdx.x;
    int v = (tid < SCAN_BLOCKS) ? bsum[tid] : 0;
    sd[tid] = v;
    __syncthreads();
    for (int off = 1; off < 512; off <<= 1) {
        int t = (tid >= off) ? sd[tid - off] : 0;
        __syncthreads();
        sd[tid] += t;
        __syncthreads();
    }
    if (tid < SCAN_BLOCKS) bsum[tid] = sd[tid] - v;   // exclusive
    if (tid == 0) indptr[NN] = EE;
}

__global__ void scanC_kernel(const int* __restrict__ cnt, const int* __restrict__ bsum,
                             int* __restrict__ indptr, int* __restrict__ cursor) {
    __shared__ int sd[256];
    int i = blockIdx.x * 256 + threadIdx.x;
    int c = (i < NN) ? cnt[i] : 0;
    sd[threadIdx.x] = c;
    __syncthreads();
    for (int off = 1; off < 256; off <<= 1) {
        int v = (threadIdx.x >= off) ? sd[threadIdx.x - off] : 0;
        __syncthreads();
        sd[threadIdx.x] += v;
        __syncthreads();
    }
    int excl = bsum[blockIdx.x] + sd[threadIdx.x] - c;
    if (i < NN) { indptr[i] = excl; cursor[i] = excl; }
}

__global__ void fill_kernel(const void* __restrict__ eidx, int* __restrict__ cursor,
                            int* __restrict__ srcs) {
    int e = blockIdx.x * 256 + threadIdx.x;
    int s, d;
    if (edge_is64(eidx)) {
        const long long* q = (const long long*)eidx;
        s = (int)q[e];
        d = (int)q[EE + e];
    } else {
        const int* q = (const int*)eidx;
        s = q[e];
        d = q[EE + e];
    }
    int pos = atomicAdd(&cursor[d], 1);
    srcs[pos] = s;
}

// ---------------- fused [gather][bn-relu][pool] + 64x64 GEMM + col-stats -------
// f(.) = BNIN ? relu(bn(.)) : identity
// GATHER: sZ[row] = f(A[row]) + sum_{e in CSR(row)} f(A[src[e]]) ; else f(A[row])
// POOL  : pooled[batch[row]] += f(A[row])   (the self term)
// then out = sZ @ W + bias; col sum/sumsq of out into osum/osq.
template <bool GATHER, bool BNIN, bool POOL>
__global__ void __launch_bounds__(256) agg_gemm_kernel(
    const float* __restrict__ A,
    const int* __restrict__ indptr, const int* __restrict__ srcs,
    const float* __restrict__ ssum_in, const float* __restrict__ ssq_in,
    const float* __restrict__ gam, const float* __restrict__ bet,
    const void* __restrict__ batch, float* __restrict__ pooled,
    const float* __restrict__ W, const float* __restrict__ bias,
    float* __restrict__ out, float* __restrict__ osum, float* __restrict__ osq) {
    extern __shared__ float sm[];
    float* sZ = sm;                         // MTILE * ZSTR = 8320
    float* sW = sm + MTILE * ZSTR;          // 4096
    float* sB = sW + 64 * 64;
    float* sSum = sB + 64;
    float* sSq = sSum + 64;
    float* sS = sSq + 64;
    float* sO = sS + 64;

    const int tid = threadIdx.x;
    const int lane = tid & 31;
    const int wid = tid >> 5;

    {
        float4* sW4 = (float4*)sW;
        const float4* W4 = (const float4*)W;
#pragma unroll
        for (int i = 0; i < 4; i++) sW4[tid + i * 256] = W4[tid + i * 256];
    }
    if (tid < 64) {
        sB[tid] = bias[tid];
        sSum[tid] = 0.f;
        sSq[tid] = 0.f;
        if (BNIN) {
            float m = ssum_in[tid] * (1.0f / NN);
            float v = ssq_in[tid] * (1.0f / NN) - m * m;
            float s = gam[tid] * rsqrtf(v + BN_EPS);
            sS[tid] = s;
            sO[tid] = bet[tid] - m * s;
        }
    }
    if (BNIN) __syncthreads();  // phase A reads sS/sO

    // ---- phase A: warp-per-row; lane owns 2 columns
    const int base = blockIdx.x * MTILE;
    float2 bns, bno;
    if (BNIN) {
        bns = *(const float2*)(sS + lane * 2);
        bno = *(const float2*)(sO + lane * 2);
    }
    const bool b64 = POOL ? batch_is64(batch) : false;

#pragma unroll 1
    for (int j = 0; j < MTILE / 8; j++) {
        const int rloc = j * 8 + wid;
        const int r = base + rloc;
        if (r < NN) {
            float2 acc = *(const float2*)(A + (size_t)r * 64 + lane * 2);
            if (BNIN) acc = bn2(acc, bns, bno);
            if (POOL) {
                int g = b64 ? (int)((const long long*)batch)[r]
                            : ((const int*)batch)[r];
                float* pb = pooled + (size_t)g * 64 + lane * 2;
                asm volatile("red.global.add.f32 [%0], %1;" :: "l"(pb), "f"(acc.x) : "memory");
                asm volatile("red.global.add.f32 [%0], %1;" :: "l"(pb + 1), "f"(acc.y) : "memory");
            }
            if (GATHER) {
                int e = indptr[r];
                const int end = indptr[r + 1];
                for (; e + 4 <= end; e += 4) {
                    int s0 = srcs[e], s1 = srcs[e + 1], s2 = srcs[e + 2], s3 = srcs[e + 3];
                    float2 v0 = *(const float2*)(A + (size_t)s0 * 64 + lane * 2);
                    float2 v1 = *(const float2*)(A + (size_t)s1 * 64 + lane * 2);
                    float2 v2 = *(const float2*)(A + (size_t)s2 * 64 + lane * 2);
                    float2 v3 = *(const float2*)(A + (size_t)s3 * 64 + lane * 2);
                    if (BNIN) {
                        v0 = bn2(v0, bns, bno); v1 = bn2(v1, bns, bno);
                        v2 = bn2(v2, bns, bno); v3 = bn2(v3, bns, bno);
                    }
                    acc.x += (v0.x + v1.x) + (v2.x + v3.x);
                    acc.y += (v0.y + v1.y) + (v2.y + v3.y);
                }
                for (; e < end; e++) {
                    int s0 = srcs[e];
                    float2 v0 = *(const float2*)(A + (size_t)s0 * 64 + lane * 2);
                    if (BNIN) v0 = bn2(v0, bns, bno);
                    acc.x += v0.x;
                    acc.y += v0.y;
                }
            }
            sZ[rloc * ZSTR + lane * 2] = acc.x;
            sZ[rloc * ZSTR + lane * 2 + 1] = acc.y;
        }
    }
    __syncthreads();

    // ---- phase B: GEMM, thread = 4 rows x 8 cols
    const int rg = tid >> 3;   // 0..31  -> rows rg*4 .. rg*4+3
    const int cg = tid & 7;    // 0..7
    const int j0 = cg * 8;
    float acc[4][8];
#pragma unroll
    for (int i = 0; i < 4; i++)
#pragma unroll
        for (int j = 0; j < 8; j++) acc[i][j] = sB[j0 + j];

#pragma unroll 4
    for (int k = 0; k < 64; k++) {
        float zv[4];
#pragma unroll
        for (int i = 0; i < 4; i++) zv[i] = sZ[(rg * 4 + i) * ZSTR + k];
        float4 w0 = *(const float4*)(sW + k * 64 + j0);
        float4 w1 = *(const float4*)(sW + k * 64 + j0 + 4);
        float wv[8] = {w0.x, w0.y, w0.z, w0.w, w1.x, w1.y, w1.z, w1.w};
#pragma unroll
        for (int i = 0; i < 4; i++)
#pragma unroll
            for (int j = 0; j < 8; j++)
                acc[i][j] = fmaf(zv[i], wv[j], acc[i][j]);
    }

    // ---- store + column stats
    float csum[8], csq[8];
#pragma unroll
    for (int j = 0; j < 8; j++) { csum[j] = 0.f; csq[j] = 0.f; }
#pragma unroll
    for (int i = 0; i < 4; i++) {
        const int r = base + rg * 4 + i;
        if (r < NN) {
            float4 o0 = make_float4(acc[i][0], acc[i][1], acc[i][2], acc[i][3]);
            float4 o1 = make_float4(acc[i][4], acc[i][5], acc[i][6], acc[i][7]);
            *(float4*)(out + (size_t)r * 64 + j0) = o0;
            *(float4*)(out + (size_t)r * 64 + j0 + 4) = o1;
#pragma unroll
            for (int j = 0; j < 8; j++) {
                csum[j] += acc[i][j];
                csq[j] += acc[i][j] * acc[i][j];
            }
        }
    }
#pragma unroll
    for (int j = 0; j < 8; j++) {
        csum[j] += __shfl_down_sync(0xffffffffu, csum[j], 8);
        csq[j] += __shfl_down_sync(0xffffffffu, csq[j], 8);
        csum[j] += __shfl_down_sync(0xffffffffu, csum[j], 16);
        csq[j] += __shfl_down_sync(0xffffffffu, csq[j], 16);
    }
    if (lane < 8) {
#pragma unroll
        for (int j = 0; j < 8; j++) {
            atomicAdd(&sSum[j0 + j], csum[j]);
            atomicAdd(&sSq[j0 + j], csq[j]);
        }
    }
    __syncthreads();
    if (tid < 64) {
        atomicAdd(&osum[tid], sSum[tid]);
        atomicAdd(&osq[tid], sSq[tid]);
    }
}

// ---------------- standalone pool with bn+relu (for the last layer) -----------
__global__ void poolbn_kernel(const float* __restrict__ X,
                              const float* __restrict__ ssum,
                              const float* __restrict__ ssq,
                              const float* __restrict__ gam,
                              const float* __restrict__ bet,
                              const void* __restrict__ batch,
                              float* __restrict__ pooled) {
    __shared__ float sS[64], sO[64];
    const int tid = threadIdx.x;
    if (tid < 64) {
        float m = ssum[tid] * (1.0f / NN);
        float v = ssq[tid] * (1.0f / NN) - m * m;
        float s = gam[tid] * rsqrtf(v + BN_EPS);
        sS[tid] = s;
        sO[tid] = bet[tid] - m * s;
    }
    __syncthreads();
    long i = (long)blockIdx.x * 256 + tid;   // grid exact: NN*16/256
    const int row = (int)(i >> 4);
    const int k = (int)(i & 15) * 4;
    float4 v = ((const float4*)X)[i];
    v.x = fmaxf(fmaf(v.x, sS[k + 0], sO[k + 0]), 0.f);
    v.y = fmaxf(fmaf(v.y, sS[k + 1], sO[k + 1]), 0.f);
    v.z = fmaxf(fmaf(v.z, sS[k + 2], sO[k + 2]), 0.f);
    v.w = fmaxf(fmaf(v.w, sS[k + 3], sO[k + 3]), 0.f);
    int g = batch_is64(batch) ? (int)((const long long*)batch)[row]
                              : ((const int*)batch)[row];
    float* basep = pooled + (size_t)g * 64 + k;
    asm volatile("red.global.add.v4.f32 [%0], {%1,%2,%3,%4};"
                 :: "l"(basep), "f"(v.x), "f"(v.y), "f"(v.z), "f"(v.w)
                 : "memory");
}

// ---------------- final jumping-knowledge readout -------------------------------
__global__ void readout_kernel(const float* __restrict__ w0, const float* __restrict__ b0,
                               const float* __restrict__ w1, const float* __restrict__ b1,
                               const float* __restrict__ w2, const float* __restrict__ b2,
                               float* __restrict__ out) {
    int t = blockIdx.x * blockDim.x + threadIdx.x;
    if (t >= GG * CC) return;
    int g = t / CC, c = t % CC;
    float acc = b0[c] + b1[c] + b2[c];
    const float* p0 = g_pooled + (size_t)g * 64;
    const float* p1 = g_pooled + (size_t)GG * 64 + (size_t)g * 64;
    const float* p2 = g_pooled + (size_t)2 * GG * 64 + (size_t)g * 64;
#pragma unroll
    for (int f = 0; f < 64; f++) {
        acc = fmaf(p0[f], w0[f * CC + c], acc);
        acc = fmaf(p1[f], w1[f * CC + c], acc);
        acc = fmaf(p2[f], w2[f * CC + c], acc);
    }
    out[t] = acc;
}

// ---------------- launch --------------------------------------------------------
extern "C" void kernel_launch(void* const* d_in, const int* in_sizes, int n_in,
                              void* d_out, int out_size) {
    const float* x = (const float*)d_in[0];
    const void* eidx = d_in[1];
    const void* batch = d_in[2];

    void *tp, *u0p, *u1p, *statp, *pooledp;
    void *cntp, *indp, *curp, *srcp, *bsump;
    cudaGetSymbolAddress(&tp, g_t);
    cudaGetSymbolAddress(&u0p, g_u0);
    cudaGetSymbolAddress(&u1p, g_u1);
    cudaGetSymbolAddress(&statp, g_stat);
    cudaGetSymbolAddress(&pooledp, g_pooled);
    cudaGetSymbolAddress(&cntp, g_cnt);
    cudaGetSymbolAddress(&indp, g_indptr);
    cudaGetSymbolAddress(&curp, g_cursor);
    cudaGetSymbolAddress(&srcp, g_srcs);
    cudaGetSymbolAddress(&bsump, g_bsum);

    float* t = (float*)tp;
    float* u0 = (float*)u0p;
    float* u1 = (float*)u1p;
    float* stat = (float*)statp;
    float* pooled = (float*)pooledp;
    int* cnt = (int*)cntp;
    int* indptr = (int*)indp;
    int* cursor = (int*)curp;
    int* srcs = (int*)srcp;
    int* bsum = (int*)bsump;

    const int EDGE_BLOCKS = EE / 256;                   // 6250
    const int FUSE_BLOCKS = (NN + MTILE - 1) / MTILE;   // 782
    const int ELEM_BLOCKS = NN * 16 / 256;              // 6250
    const int INIT_BLOCKS = (3 * GG * HH + 255) / 256;  // 750

    const int SMEM_BYTES = (MTILE * ZSTR + 64 * 64 + 64 * 5) * sizeof(float);
    static bool attr_set = false;
    if (!attr_set) {
        cudaFuncSetAttribute(agg_gemm_kernel<true, false, true>,
                             cudaFuncAttributeMaxDynamicSharedMemorySize, SMEM_BYTES);
        cudaFuncSetAttribute(agg_gemm_kernel<true, true, true>,
                             cudaFuncAttributeMaxDynamicSharedMemorySize, SMEM_BYTES);
        cudaFuncSetAttribute(agg_gemm_kernel<false, true, false>,
                             cudaFuncAttributeMaxDynamicSharedMemorySize, SMEM_BYTES);
        attr_set = true;
    }

    // CSR build
    init_kernel<<<INIT_BLOCKS, 256>>>(cnt, stat, pooled);
    count_kernel<<<EDGE_BLOCKS, 256>>>(eidx, cnt);
    scanA_kernel<<<SCAN_BLOCKS, 256>>>(cnt, bsum);
    scanB_kernel<<<1, 512>>>(bsum, indptr);
    scanC_kernel<<<SCAN_BLOCKS, 256>>>(cnt, bsum, indptr, cursor);
    fill_kernel<<<EDGE_BLOCKS, 256>>>(eidx, cursor, srcs);

    const float* w1_0  = (const float*)d_in[3];
    const float* b1_0  = (const float*)d_in[4];
    const float* g1_0  = (const float*)d_in[5];
    const float* be1_0 = (const float*)d_in[6];
    const float* w2_0  = (const float*)d_in[7];
    const float* b2_0  = (const float*)d_in[8];
    const float* bng0  = (const float*)d_in[9];
    const float* bnb0  = (const float*)d_in[10];
    const float* w1_1  = (const float*)d_in[11];
    const float* b1_1  = (const float*)d_in[12];
    const float* g1_1  = (const float*)d_in[13];
    const float* be1_1 = (const float*)d_in[14];
    const float* w2_1  = (const float*)d_in[15];
    const float* b2_1  = (const float*)d_in[16];
    const float* bng1  = (const float*)d_in[17];
    const float* bnb1  = (const float*)d_in[18];

    float* st0 = stat;         // t0 sum/sq @0/64, u0 sum/sq @128/192
    float* st1 = stat + 256;   // t1 sum/sq @0/64, u1 sum/sq @128/192

    // ---- layer 0: gather(x) + GEMM1 + pool(x into slot 0)
    agg_gemm_kernel<true, false, true><<<FUSE_BLOCKS, 256, SMEM_BYTES>>>(
        x, indptr, srcs, nullptr, nullptr, nullptr, nullptr,
        batch, pooled,
        w1_0, b1_0, t, st0, st0 + 64);
    agg_gemm_kernel<false, true, false><<<FUSE_BLOCKS, 256, SMEM_BYTES>>>(
        t, nullptr, nullptr, st0, st0 + 64, g1_0, be1_0,
        nullptr, nullptr,
        w2_0, b2_0, u0, st0 + 128, st0 + 192);

    // ---- layer 1: gather(h1 = relu(bn(u0))) + GEMM1 + pool(h1 into slot 1)
    agg_gemm_kernel<true, true, true><<<FUSE_BLOCKS, 256, SMEM_BYTES>>>(
        u0, indptr, srcs, st0 + 128, st0 + 192, bng0, bnb0,
        batch, pooled + (size_t)GG * HH,
        w1_1, b1_1, t, st1, st1 + 64);
    agg_gemm_kernel<false, true, false><<<FUSE_BLOCKS, 256, SMEM_BYTES>>>(
        t, nullptr, nullptr, st1, st1 + 64, g1_1, be1_1,
        nullptr, nullptr,
        w2_1, b2_1, u1, st1 + 128, st1 + 192);

    // ---- h2 pooling (needs u1 stats)
    poolbn_kernel<<<ELEM_BLOCKS, 256>>>(
        u1, st1 + 128, st1 + 192, bng1, bnb1, batch, pooled + (size_t)2 * GG * HH);

    readout_kernel<<<(GG * CC + 255) / 256, 256>>>(
        (const float*)d_in[19], (const float*)d_in[20],
        (const float*)d_in[21], (const float*)d_in[22],
        (const float*)d_in[23], (const float*)d_in[24],
        (float*)d_out);
}